// round 7
// baseline (speedup 1.0000x reference)
#include <cuda_runtime.h>
#include <cstdint>

// ---------------------------------------------------------------------------
// MinimalQuantumLayer via Heisenberg picture.
//
// <Z_q> = <psi1| R1' L2' (R2' Z_q R2) L2 R1 |psi1>,  psi1 = product state
// after layer-1 RX. CNOT rings (Clifford) are folded at COMPILE TIME into
// Pauli-string conjugations (symplectic rep + Aaronson-Gottesman phase rule);
// RX layer 2 expands each Z_j -> cos(w)Z_j + sin(w)Y_j. Result: 36 Pauli
// string terms total, each evaluated as a product of per-qubit Bloch
// expectations (<X>=sin t, <Y>=-sin(w1)cos t, <Z>=cos(w1)cos t, t = x*pi/2).
// Two patches per thread packed in f32x2 lanes. No state vector, no smem.
// ---------------------------------------------------------------------------

typedef unsigned long long u64x;

static __device__ __forceinline__ u64x pack2(float lo, float hi) {
    u64x r;
    asm("mov.b64 %0, {%1, %2};" : "=l"(r)
        : "r"(__float_as_uint(lo)), "r"(__float_as_uint(hi)));
    return r;
}
static __device__ __forceinline__ void unpack2(u64x v, float& lo, float& hi) {
    unsigned a, b;
    asm("mov.b64 {%0, %1}, %2;" : "=r"(a), "=r"(b) : "l"(v));
    lo = __uint_as_float(a); hi = __uint_as_float(b);
}
static __device__ __forceinline__ u64x bcast2(float f) { return pack2(f, f); }
static __device__ __forceinline__ u64x fma2(u64x a, u64x b, u64x c) {
    u64x d;
    asm("fma.rn.f32x2 %0, %1, %2, %3;" : "=l"(d) : "l"(a), "l"(b), "l"(c));
    return d;
}
static __device__ __forceinline__ u64x mul2(u64x a, u64x b) {
    u64x d;
    asm("mul.rn.f32x2 %0, %1, %2;" : "=l"(d) : "l"(a), "l"(b));
    return d;
}
static __device__ __forceinline__ u64x add2(u64x a, u64x b) {
    u64x d;
    asm("add.rn.f32x2 %0, %1, %2;" : "=l"(d) : "l"(a), "l"(b));
    return d;
}
static __device__ __forceinline__ u64x neg2(u64x a) { return a ^ 0x8000000080000000ULL; }

// sin/cos on [0, pi/4], packed lanes. Taylor deg 8 (cos) / deg 7 (sin).
static __device__ __forceinline__ void sincos2(u64x t, u64x& c, u64x& s) {
    const u64x ONE = bcast2(1.0f);
    const u64x C2 = bcast2(-0.5f),          C4 = bcast2(1.0f / 24.0f),
               C6 = bcast2(-1.0f / 720.0f), C8 = bcast2(1.0f / 40320.0f);
    const u64x S3 = bcast2(-1.0f / 6.0f),   S5 = bcast2(1.0f / 120.0f),
               S7 = bcast2(-1.0f / 5040.0f);
    u64x t2 = mul2(t, t);
    u64x cp = fma2(C8, t2, C6);
    cp = fma2(cp, t2, C4);
    cp = fma2(cp, t2, C2);
    c  = fma2(cp, t2, ONE);
    u64x sp = fma2(S7, t2, S5);
    sp = fma2(sp, t2, S3);
    sp = fma2(sp, t2, ONE);
    s  = mul2(sp, t);
}

// ---------------- compile-time Pauli-string machinery ----------------------
// String = i^ph * prod_q sigma(x_q, z_q), letters (x,z): (0,0)=I (1,0)=X
// (0,1)=Z (1,1)=Y (per-qubit i^{xz} folded into letter). ph in {0,2} => +-1.
struct PS { int x, z, ph; };

// Conjugation by CNOT(c,t) (self-inverse): x_t ^= x_c; z_c ^= z_t;
// sign flip iff x_c & z_t & (x_t ^ z_c ^ 1)   [Aaronson-Gottesman].
static __host__ __device__ constexpr PS conj_cnot(PS p, int c, int t) {
    const int xc = (p.x >> c) & 1, zc = (p.z >> c) & 1;
    const int xt = (p.x >> t) & 1, zt = (p.z >> t) & 1;
    const int flip = xc & zt & (xt ^ zc ^ 1);
    return PS{ p.x ^ (xc << t), p.z ^ (zt << c), (p.ph + 2 * flip) & 3 };
}
// Ring = CNOT(0,1),CNOT(1,2),CNOT(2,3),CNOT(3,0) applied in that order to the
// state; conjugation R' P R applies gate conjugations in reverse order.
static __host__ __device__ constexpr PS conj_ring(PS p) {
    p = conj_cnot(p, 3, 0);
    p = conj_cnot(p, 2, 3);
    p = conj_cnot(p, 1, 2);
    p = conj_cnot(p, 0, 1);
    return p;
}
static __host__ __device__ constexpr PS mul_ps(PS a, PS b) {
    int ph = a.ph + b.ph;
    for (int q = 0; q < 4; ++q) {
        const int x1 = (a.x >> q) & 1, z1 = (a.z >> q) & 1;
        const int x2 = (b.x >> q) & 1, z2 = (b.z >> q) & 1;
        ph += x1 * z1 + x2 * z2 + 2 * (z1 & x2) - ((x1 ^ x2) & (z1 ^ z2));
    }
    return PS{ a.x ^ b.x, a.z ^ b.z, ((ph % 4) + 4) & 3 };
}

struct TermTab {
    int off[5];
    int S[4];          // support mask of R2-conjugated Z_q
    int let[36][4];    // 0=I 1=X 2=Z 3=Y
    int sgn[36];
    int smask[36];     // bit j: factor uses sin(w2_j) (else cos)
};

static __host__ __device__ constexpr TermTab build_terms() {
    TermTab T{};
    int n = 0;
    for (int o = 0; o < 4; ++o) {
        T.off[o] = n;
        const PS Pq = conj_ring(PS{0, 1 << o, 0});   // R2' Z_o R2: pure Z-string
        const int S = Pq.z;
        T.S[o] = S;
        for (int m = 0; m < 16; ++m) {
            if (m & ~S) continue;
            PS prod{0, 0, 0};
            for (int j = 0; j < 4; ++j) {
                if (!((S >> j) & 1)) continue;
                const PS base = ((m >> j) & 1) ? PS{1 << j, 1 << j, 0}   // Y_j
                                               : PS{0, 1 << j, 0};      // Z_j
                prod = mul_ps(prod, conj_ring(base));                   // R1-conj
            }
            for (int q = 0; q < 4; ++q) {
                const int xb = (prod.x >> q) & 1, zb = (prod.z >> q) & 1;
                T.let[n][q] = xb + 2 * zb;
            }
            T.sgn[n]   = (prod.ph == 0) ? 1 : ((prod.ph == 2) ? -1 : 0);
            T.smask[n] = m;
            ++n;
        }
    }
    T.off[4] = n;
    return T;
}

// ---------------- main kernel ---------------------------------------------
// 262144 threads = 32 (batch) * 128 (rows) * 64 (column pairs);
// lane lo = patch at column 2*c2, lane hi = column 2*c2+1.
__global__ void __launch_bounds__(256, 3)
qmain_kernel(const float* __restrict__ x, const float* __restrict__ w8,
             float* __restrict__ out) {
    constexpr TermTab TT = build_terms();

    // warp-uniform weight trig (|w| <= 0.1 -> short Taylor, full angle)
    float c1[4], s1[4], c2w[4], s2w[4];
    {
        const float4 wa = __ldg(reinterpret_cast<const float4*>(w8));
        const float4 wb = __ldg(reinterpret_cast<const float4*>(w8) + 1);
        const float w1[4] = {wa.x, wa.y, wa.z, wa.w};
        const float w2[4] = {wb.x, wb.y, wb.z, wb.w};
#pragma unroll
        for (int q = 0; q < 4; ++q) {
            const float a = w1[q], a2 = a * a;
            c1[q] = 1.0f + a2 * (-0.5f + a2 * (1.0f / 24.0f));
            s1[q] = a * (1.0f + a2 * (-1.0f / 6.0f + a2 * (1.0f / 120.0f)));
            const float b = w2[q], b2 = b * b;
            c2w[q] = 1.0f + b2 * (-0.5f + b2 * (1.0f / 24.0f));
            s2w[q] = b * (1.0f + b2 * (-1.0f / 6.0f + b2 * (1.0f / 120.0f)));
        }
    }

    const int idx = blockIdx.x * 256 + threadIdx.x;
    const int c2 = idx & 63;
    const int r  = (idx >> 6) & 127;
    const int b  = idx >> 13;

    const int xoff = ((b * 256 + 2 * r) * 256) + 4 * c2;
    const float4 p0 = *reinterpret_cast<const float4*>(x + xoff);        // row 2r
    const float4 p1 = *reinterpret_cast<const float4*>(x + xoff + 256);  // row 2r+1

    // half-angle theta/2 = x*pi/4 in [0, pi/4]
    const u64x PI4 = bcast2(0.78539816339744831f);
    u64x ch[4], sh[4];
    sincos2(mul2(pack2(p0.x, p0.z), PI4), ch[0], sh[0]);
    sincos2(mul2(pack2(p0.y, p0.w), PI4), ch[1], sh[1]);
    sincos2(mul2(pack2(p1.x, p1.z), PI4), ch[2], sh[2]);
    sincos2(mul2(pack2(p1.y, p1.w), PI4), ch[3], sh[3]);

    // Bloch expectations per qubit: <X>=sin t, <Y>=-s1*cos t, <Z>=c1*cos t
    const u64x ONEb = bcast2(1.0f);
    u64x ex[4], ey[4], ez[4];
#pragma unroll
    for (int q = 0; q < 4; ++q) {
        const u64x s2x = add2(sh[q], sh[q]);            // 2 sin(t/2)
        ex[q] = mul2(s2x, ch[q]);                       // sin t
        const u64x ct = fma2(neg2(s2x), sh[q], ONEb);   // cos t = 1 - 2 sin^2
        ey[q] = mul2(bcast2(-s1[q]), ct);
        ez[q] = mul2(bcast2(c1[q]), ct);
    }

    // evaluate the 4 observables: sum over compile-time Pauli terms
    u64x zo[4];
#pragma unroll
    for (int o = 0; o < 4; ++o) {
        u64x acc = bcast2(0.0f);
#pragma unroll
        for (int ti = TT.off[o]; ti < TT.off[o + 1]; ++ti) {
            float coef = (float)TT.sgn[ti];
#pragma unroll
            for (int j = 0; j < 4; ++j)
                if ((TT.S[o] >> j) & 1)
                    coef *= ((TT.smask[ti] >> j) & 1) ? s2w[j] : c2w[j];
            u64x m = bcast2(coef);
#pragma unroll
            for (int q = 0; q < 4; ++q) {
                const int L = TT.let[ti][q];
                if (L == 1)      m = mul2(m, ex[q]);
                else if (L == 2) m = mul2(m, ez[q]);
                else if (L == 3) m = mul2(m, ey[q]);
            }
            acc = add2(acc, m);
        }
        zo[o] = acc;
    }

    float z0a, z0b, z1a, z1b, z2a, z2b, z3a, z3b;
    unpack2(zo[0], z0a, z0b);
    unpack2(zo[1], z1a, z1b);
    unpack2(zo[2], z2a, z2b);
    unpack2(zo[3], z3a, z3b);

    const int o = ((b * 128 + r) * 128 + 2 * c2) * 4;
    reinterpret_cast<float4*>(out + o)[0] = make_float4(z0a, z1a, z2a, z3a);
    reinterpret_cast<float4*>(out + o)[1] = make_float4(z0b, z1b, z2b, z3b);
}

// ---------------- launch ----------------------------------------------------
extern "C" void kernel_launch(void* const* d_in, const int* in_sizes, int n_in,
                              void* d_out, int out_size) {
    const float* x = (const float*)d_in[0];
    const float* w = (const float*)d_in[1];
    if (n_in >= 2 && in_sizes[0] == 8) {  // defensive: metadata order swap
        const float* t = x; x = w; w = t;
    }
    qmain_kernel<<<1024, 256>>>(x, w, (float*)d_out);
}

// round 8
// speedup vs baseline: 13.1801x; 13.1801x over previous
#include <cuda_runtime.h>
#include <cstdint>

// ---------------------------------------------------------------------------
// MinimalQuantumLayer via Heisenberg picture — all Pauli-term structure
// lowered to compile-time immediates through templates (R7 lesson: an
// indexed constexpr aggregate gets materialized in local memory; templated
// constexpr scalar extraction does not).
//
// <Z_q> = <psi1| R1' L2' (R2' Z_q R2) L2 R1 |psi1>, psi1 = product state
// after layer-1 RX. CNOT rings conjugated at compile time (symplectic +
// Aaronson-Gottesman sign rule); RX layer 2 expands Z_j -> cos w Z_j +
// sin w Y_j. 36 Pauli-string terms total; product state => each term is a
// product of per-qubit Bloch values (<X>=sin t, <Y>=-sin w1 cos t,
// <Z>=cos w1 cos t, t = x*pi/2). Two patches per thread in f32x2 lanes.
// ---------------------------------------------------------------------------

typedef unsigned long long u64x;

static __device__ __forceinline__ u64x pack2(float lo, float hi) {
    u64x r;
    asm("mov.b64 %0, {%1, %2};" : "=l"(r)
        : "r"(__float_as_uint(lo)), "r"(__float_as_uint(hi)));
    return r;
}
static __device__ __forceinline__ void unpack2(u64x v, float& lo, float& hi) {
    unsigned a, b;
    asm("mov.b64 {%0, %1}, %2;" : "=r"(a), "=r"(b) : "l"(v));
    lo = __uint_as_float(a); hi = __uint_as_float(b);
}
static __device__ __forceinline__ u64x bcast2(float f) { return pack2(f, f); }
static __device__ __forceinline__ u64x fma2(u64x a, u64x b, u64x c) {
    u64x d;
    asm("fma.rn.f32x2 %0, %1, %2, %3;" : "=l"(d) : "l"(a), "l"(b), "l"(c));
    return d;
}
static __device__ __forceinline__ u64x mul2(u64x a, u64x b) {
    u64x d;
    asm("mul.rn.f32x2 %0, %1, %2;" : "=l"(d) : "l"(a), "l"(b));
    return d;
}
static __device__ __forceinline__ u64x add2(u64x a, u64x b) {
    u64x d;
    asm("add.rn.f32x2 %0, %1, %2;" : "=l"(d) : "l"(a), "l"(b));
    return d;
}
static __device__ __forceinline__ u64x neg2(u64x a) { return a ^ 0x8000000080000000ULL; }

// sin/cos on [0, pi/4], packed lanes. Taylor deg 8 (cos) / deg 7 (sin).
static __device__ __forceinline__ void sincos2(u64x t, u64x& c, u64x& s) {
    const u64x ONE = bcast2(1.0f);
    const u64x C2 = bcast2(-0.5f),          C4 = bcast2(1.0f / 24.0f),
               C6 = bcast2(-1.0f / 720.0f), C8 = bcast2(1.0f / 40320.0f);
    const u64x S3 = bcast2(-1.0f / 6.0f),   S5 = bcast2(1.0f / 120.0f),
               S7 = bcast2(-1.0f / 5040.0f);
    u64x t2 = mul2(t, t);
    u64x cp = fma2(C8, t2, C6);
    cp = fma2(cp, t2, C4);
    cp = fma2(cp, t2, C2);
    c  = fma2(cp, t2, ONE);
    u64x sp = fma2(S7, t2, S5);
    sp = fma2(sp, t2, S3);
    sp = fma2(sp, t2, ONE);
    s  = mul2(sp, t);
}

// ---------------- compile-time Pauli-string machinery ----------------------
struct PS { int x, z, ph; };

static __host__ __device__ constexpr PS conj_cnot(PS p, int c, int t) {
    const int xc = (p.x >> c) & 1, zc = (p.z >> c) & 1;
    const int xt = (p.x >> t) & 1, zt = (p.z >> t) & 1;
    const int flip = xc & zt & (xt ^ zc ^ 1);
    return PS{ p.x ^ (xc << t), p.z ^ (zt << c), (p.ph + 2 * flip) & 3 };
}
static __host__ __device__ constexpr PS conj_ring(PS p) {
    p = conj_cnot(p, 3, 0);
    p = conj_cnot(p, 2, 3);
    p = conj_cnot(p, 1, 2);
    p = conj_cnot(p, 0, 1);
    return p;
}
static __host__ __device__ constexpr PS mul_ps(PS a, PS b) {
    int ph = a.ph + b.ph;
    for (int q = 0; q < 4; ++q) {
        const int x1 = (a.x >> q) & 1, z1 = (a.z >> q) & 1;
        const int x2 = (b.x >> q) & 1, z2 = (b.z >> q) & 1;
        ph += x1 * z1 + x2 * z2 + 2 * (z1 & x2) - ((x1 ^ x2) & (z1 ^ z2));
    }
    return PS{ a.x ^ b.x, a.z ^ b.z, ((ph % 4) + 4) & 3 };
}

struct TermTab {
    int off[5];
    int S[4];          // support mask of R2-conjugated Z_q
    int let[36][4];    // 0=I 1=X 2=Z 3=Y
    int sgn[36];
    int smask[36];     // bit j: factor uses sin(w2_j) (else cos)
};

static __host__ __device__ constexpr TermTab build_terms() {
    TermTab T{};
    int n = 0;
    for (int o = 0; o < 4; ++o) {
        T.off[o] = n;
        const PS Pq = conj_ring(PS{0, 1 << o, 0});   // R2' Z_o R2: pure Z-string
        const int S = Pq.z;
        T.S[o] = S;
        for (int m = 0; m < 16; ++m) {
            if (m & ~S) continue;
            PS prod{0, 0, 0};
            for (int j = 0; j < 4; ++j) {
                if (!((S >> j) & 1)) continue;
                const PS base = ((m >> j) & 1) ? PS{1 << j, 1 << j, 0}   // Y_j
                                               : PS{0, 1 << j, 0};      // Z_j
                prod = mul_ps(prod, conj_ring(base));                   // R1-conj
            }
            for (int q = 0; q < 4; ++q) {
                const int xb = (prod.x >> q) & 1, zb = (prod.z >> q) & 1;
                T.let[n][q] = xb + 2 * zb;
            }
            T.sgn[n]   = (prod.ph == 0) ? 1 : ((prod.ph == 2) ? -1 : 0);
            T.smask[n] = m;
            ++n;
        }
    }
    T.off[4] = n;
    return T;
}

static constexpr TermTab TTC = build_terms();   // compile-time only

// ---------------- templated, fully-folded term evaluation -------------------
struct Bloch { u64x ex[4], ey[4], ez[4]; };
struct WCoef { float c2w[4], s2w[4]; };

template <int L, int Q>
static __device__ __forceinline__ u64x getB(const Bloch& B) {
    if constexpr (L == 1) return B.ex[Q];
    else if constexpr (L == 2) return B.ez[Q];
    else return B.ey[Q];
}

template <int TI>
static __device__ __forceinline__ u64x pprod(const Bloch& B) {
    constexpr int L0 = TTC.let[TI][0], L1 = TTC.let[TI][1],
                  L2 = TTC.let[TI][2], L3 = TTC.let[TI][3];
    constexpr int first = L0 ? 0 : (L1 ? 1 : (L2 ? 2 : 3));
    u64x m = getB<(first == 0 ? L0 : first == 1 ? L1 : first == 2 ? L2 : L3),
                  first>(B);
    if constexpr (first < 1 && L1 != 0) m = mul2(m, getB<L1, 1>(B));
    if constexpr (first < 2 && L2 != 0) m = mul2(m, getB<L2, 2>(B));
    if constexpr (first < 3 && L3 != 0) m = mul2(m, getB<L3, 3>(B));
    return m;
}

template <int O, int TI, int TE>
struct TermSum {
    static __device__ __forceinline__ u64x go(const Bloch& B, const WCoef& W) {
        constexpr int S = TTC.S[O], sm = TTC.smask[TI];
        float c = (float)TTC.sgn[TI];
        if constexpr ((S >> 0) & 1) c *= ((sm >> 0) & 1) ? W.s2w[0] : W.c2w[0];
        if constexpr ((S >> 1) & 1) c *= ((sm >> 1) & 1) ? W.s2w[1] : W.c2w[1];
        if constexpr ((S >> 2) & 1) c *= ((sm >> 2) & 1) ? W.s2w[2] : W.c2w[2];
        if constexpr ((S >> 3) & 1) c *= ((sm >> 3) & 1) ? W.s2w[3] : W.c2w[3];
        return fma2(pprod<TI>(B), bcast2(c), TermSum<O, TI + 1, TE>::go(B, W));
    }
};
template <int O, int TE>
struct TermSum<O, TE, TE> {
    static __device__ __forceinline__ u64x go(const Bloch&, const WCoef&) {
        return bcast2(0.0f);
    }
};

// ---------------- main kernel ---------------------------------------------
// 262144 threads = 32 (batch) * 128 (rows) * 64 (column pairs);
// lane lo = patch at column 2*c2, lane hi = column 2*c2+1.
__global__ void __launch_bounds__(256, 3)
qmain_kernel(const float* __restrict__ x, const float* __restrict__ w8,
             float* __restrict__ out) {
    // warp-uniform weight trig (|w| <= 0.1 -> short Taylor, full angle)
    WCoef W;
    float c1[4], s1[4];
    {
        const float4 wa = __ldg(reinterpret_cast<const float4*>(w8));
        const float4 wb = __ldg(reinterpret_cast<const float4*>(w8) + 1);
        const float w1[4] = {wa.x, wa.y, wa.z, wa.w};
        const float w2[4] = {wb.x, wb.y, wb.z, wb.w};
#pragma unroll
        for (int q = 0; q < 4; ++q) {
            const float a = w1[q], a2 = a * a;
            c1[q] = 1.0f + a2 * (-0.5f + a2 * (1.0f / 24.0f));
            s1[q] = a * (1.0f + a2 * (-1.0f / 6.0f + a2 * (1.0f / 120.0f)));
            const float b = w2[q], b2 = b * b;
            W.c2w[q] = 1.0f + b2 * (-0.5f + b2 * (1.0f / 24.0f));
            W.s2w[q] = b * (1.0f + b2 * (-1.0f / 6.0f + b2 * (1.0f / 120.0f)));
        }
    }

    const int idx = blockIdx.x * 256 + threadIdx.x;
    const int c2 = idx & 63;
    const int r  = (idx >> 6) & 127;
    const int b  = idx >> 13;

    const int xoff = ((b * 256 + 2 * r) * 256) + 4 * c2;
    const float4 p0 = *reinterpret_cast<const float4*>(x + xoff);        // row 2r
    const float4 p1 = *reinterpret_cast<const float4*>(x + xoff + 256);  // row 2r+1

    // half-angle theta/2 = x*pi/4 in [0, pi/4]
    const u64x PI4 = bcast2(0.78539816339744831f);
    u64x ch[4], sh[4];
    sincos2(mul2(pack2(p0.x, p0.z), PI4), ch[0], sh[0]);
    sincos2(mul2(pack2(p0.y, p0.w), PI4), ch[1], sh[1]);
    sincos2(mul2(pack2(p1.x, p1.z), PI4), ch[2], sh[2]);
    sincos2(mul2(pack2(p1.y, p1.w), PI4), ch[3], sh[3]);

    // Bloch expectations per qubit: <X>=sin t, <Y>=-s1*cos t, <Z>=c1*cos t
    const u64x ONEb = bcast2(1.0f);
    Bloch B;
#pragma unroll
    for (int q = 0; q < 4; ++q) {
        const u64x s2x = add2(sh[q], sh[q]);            // 2 sin(t/2)
        B.ex[q] = mul2(s2x, ch[q]);                     // sin t
        const u64x ct = fma2(neg2(s2x), sh[q], ONEb);   // cos t = 1 - 2 sin^2
        B.ey[q] = mul2(bcast2(-s1[q]), ct);
        B.ez[q] = mul2(bcast2(c1[q]), ct);
    }

    // 4 observables: compile-time-unrolled Pauli-term sums (no tables)
    const u64x z0 = TermSum<0, TTC.off[0], TTC.off[1]>::go(B, W);
    const u64x z1 = TermSum<1, TTC.off[1], TTC.off[2]>::go(B, W);
    const u64x z2 = TermSum<2, TTC.off[2], TTC.off[3]>::go(B, W);
    const u64x z3 = TermSum<3, TTC.off[3], TTC.off[4]>::go(B, W);

    float z0a, z0b, z1a, z1b, z2a, z2b, z3a, z3b;
    unpack2(z0, z0a, z0b);
    unpack2(z1, z1a, z1b);
    unpack2(z2, z2a, z2b);
    unpack2(z3, z3a, z3b);

    const int o = ((b * 128 + r) * 128 + 2 * c2) * 4;
    reinterpret_cast<float4*>(out + o)[0] = make_float4(z0a, z1a, z2a, z3a);
    reinterpret_cast<float4*>(out + o)[1] = make_float4(z0b, z1b, z2b, z3b);
}

// ---------------- launch ----------------------------------------------------
extern "C" void kernel_launch(void* const* d_in, const int* in_sizes, int n_in,
                              void* d_out, int out_size) {
    const float* x = (const float*)d_in[0];
    const float* w = (const float*)d_in[1];
    if (n_in >= 2 && in_sizes[0] == 8) {  // defensive: metadata order swap
        const float* t = x; x = w; w = t;
    }
    qmain_kernel<<<1024, 256>>>(x, w, (float*)d_out);
}